// round 14
// baseline (speedup 1.0000x reference)
#include <cuda_runtime.h>
#include <cuda_fp16.h>
#include <cstdint>

#define VOCAB 50000
#define DIM   768
#define NTOK  16384
#define BM    128
#define BN    96
#define KCH   64                       // K per pipeline chunk (4 k16-steps)
#define NCH   (DIM / KCH)              // 12
#define NKS   (DIM / 16)               // 48 k16-steps per row
#define NM16  (NTOK / 16)              // 1024 fragment row-groups
#define NTILE_N (DIM / BN)             // 8
#define A_STAGE_BYTES (BM * KCH * 2)   // 16 KB (fp16)
#define B_STAGE_BYTES (BN * KCH * 2)   // 12 KB
#define STAGE_BYTES   (A_STAGE_BYTES + B_STAGE_BYTES)   // 28 KB
#define GEMM_SMEM     (2 * STAGE_BYTES)   // 56 KB -> 2 CTAs/SM
#define GEMM_GRID     296              // persistent: 2 CTAs/SM
#define GEMM_THREADS  192              // 6 warps: 2(M) x 3(N), warp tile 64x32
#define COPY_ROWS 48                   // rows per copy work unit (8/warp, 6 warps)
#define NCOPY ((NTOK + COPY_ROWS - 1) / COPY_ROWS)   // 342

// compact kernel: blocks [0,64) compact, [64,64+288) W-pack
#define NB_CMP   (NTOK / 256)          // 64
#define NB_WPACK ((48 * NKS * 32) / 256)  // 288
#define NB_PACK  (NM16 / 2)            // 512: A-pack, 2 m16-groups per block

__device__ int g_cnt;
__device__ int g_tok64;               // 1 if token buffer is int64
__device__ int g_list[NTOK];          // token position (output row)
__device__ int g_tok[NTOK];           // token id (embedding row)
// Fragment-packed fp16 operands for mma.sync m16n8k16 (row.col)
__device__ uint4 Ap[NM16 * NKS * 32];
__device__ uint4 Wp[(DIM / 16) * NKS * 32];

// ---------------------------------------------------------------- utilities
__device__ __forceinline__ uint32_t f2h2(float x, float y) {
    __half2 h = __floats2half2_rn(x, y);
    return *(uint32_t*)&h;
}
__device__ __forceinline__ uint32_t smem_u32(const void* p) {
    uint32_t a;
    asm("{ .reg .u64 t; cvta.to.shared.u64 t, %1; cvt.u32.u64 %0, t; }" : "=r"(a) : "l"(p));
    return a;
}
__device__ __forceinline__ void cp16(uint32_t dst, const void* src) {
    asm volatile("cp.async.cg.shared.global [%0], [%1], 16;\n" :: "r"(dst), "l"(src));
}
__device__ __forceinline__ void mma_f16(float c[4], uint4 a, uint32_t b0, uint32_t b1) {
    asm volatile(
        "mma.sync.aligned.m16n8k16.row.col.f32.f16.f16.f32 "
        "{%0,%1,%2,%3}, {%4,%5,%6,%7}, {%8,%9}, {%0,%1,%2,%3};\n"
        : "+f"(c[0]), "+f"(c[1]), "+f"(c[2]), "+f"(c[3])
        : "r"(a.x), "r"(a.y), "r"(a.z), "r"(a.w), "r"(b0), "r"(b1));
}

// ---------------------------------------------------------------- init
__global__ void k_init() { g_cnt = 0; }

// ---------------------------------------------------------------- compact + W-pack
// Blocks [0,NB_CMP): per-block dtype detect (L2-hot) + 1 token/thread compact.
// Blocks [NB_CMP,NB_CMP+NB_WPACK): W fragment pack (independent of compact).
__global__ void k_compact(const int* __restrict__ token, const int* __restrict__ need,
                          const float* __restrict__ W) {
    const int tid = threadIdx.x;
    if (blockIdx.x < NB_CMP) {
        int odd = (tid < 128) ? token[tid * 2 + 1] : 0;
        int any = __syncthreads_or(odd != 0);
        const int is64 = !any;
        if (blockIdx.x == 0 && tid == 0) g_tok64 = is64;

        const int p = blockIdx.x * 256 + tid;        // covers NTOK exactly
        const int t = is64 ? token[2 * p] : token[p];
        if (t >= 0 && t < VOCAB && need[t]) {
            const int pos = atomicAdd(&g_cnt, 1);
            g_list[pos] = p;
            g_tok[pos]  = t;
        }
    } else {
        const int gi = (blockIdx.x - NB_CMP) * 256 + tid;  // 48*48*32
        const int lw  = gi & 31;
        const int ks  = (gi >> 5) % NKS;
        const int n16 = gi / (NKS * 32);
        const int na = n16 * 16 + (lw >> 2);
        const int nb = na + 8;
        const int k0 = ks * 16 + (lw & 3) * 2;
        uint4 o;
        o.x = f2h2(W[(size_t)k0 * DIM + na],       W[(size_t)(k0 + 1) * DIM + na]);
        o.y = f2h2(W[(size_t)(k0 + 8) * DIM + na], W[(size_t)(k0 + 9) * DIM + na]);
        o.z = f2h2(W[(size_t)k0 * DIM + nb],       W[(size_t)(k0 + 1) * DIM + nb]);
        o.w = f2h2(W[(size_t)(k0 + 8) * DIM + nb], W[(size_t)(k0 + 9) * DIM + nb]);
        Wp[(size_t)(n16 * NKS + ks) * 32 + lw] = o;
    }
}

// ---------------------------------------------------------------- A pack
// 512 blocks x 256: 2 m16-groups per block, 4 warps each, 8 gathers in flight.
__global__ void k_pack(const float* __restrict__ emb) {
    const int bid  = blockIdx.x;
    const int tid  = threadIdx.x;
    const int wid  = tid >> 5;
    const int lane = tid & 31;

    const int cnt = g_cnt;
    const int cnt_pad = (cnt + BM - 1) & ~(BM - 1);
    const int m16 = bid * 2 + (wid >> 2);
    if (m16 * 16 >= cnt_pad) return;
    const int wg = wid & 3;                      // warp within group
    const int lr = lane >> 2, lk = lane & 3;
    const int r0 = m16 * 16 + lr, r1 = r0 + 8;
    const bool v0 = r0 < cnt, v1 = r1 < cnt;
    const float* e0 = emb + (size_t)(v0 ? g_tok[r0] : 0) * DIM;
    const float* e1 = emb + (size_t)(v1 ? g_tok[r1] : 0) * DIM;
    const float2 z2 = make_float2(0.f, 0.f);
    #pragma unroll
    for (int j = 0; j < NKS / 4; j += 2) {       // 12 ksteps, 2 at a time
        const int ksA = wg * (NKS / 4) + j;
        const int kA = ksA * 16 + lk * 2;
        const int kB = kA + 16;
        const float2 a0 = v0 ? *(const float2*)(e0 + kA)     : z2;
        const float2 a2 = v0 ? *(const float2*)(e0 + kA + 8) : z2;
        const float2 a1 = v1 ? *(const float2*)(e1 + kA)     : z2;
        const float2 a3 = v1 ? *(const float2*)(e1 + kA + 8) : z2;
        const float2 b0 = v0 ? *(const float2*)(e0 + kB)     : z2;
        const float2 b2 = v0 ? *(const float2*)(e0 + kB + 8) : z2;
        const float2 b1 = v1 ? *(const float2*)(e1 + kB)     : z2;
        const float2 b3 = v1 ? *(const float2*)(e1 + kB + 8) : z2;
        uint4 oA, oB;
        oA.x = f2h2(a0.x, a0.y); oA.y = f2h2(a1.x, a1.y);
        oA.z = f2h2(a2.x, a2.y); oA.w = f2h2(a3.x, a3.y);
        oB.x = f2h2(b0.x, b0.y); oB.y = f2h2(b1.x, b1.y);
        oB.z = f2h2(b2.x, b2.y); oB.w = f2h2(b3.x, b3.y);
        Ap[(size_t)(m16 * NKS + ksA) * 32 + lane]     = oA;
        Ap[(size_t)(m16 * NKS + ksA + 1) * 32 + lane] = oB;
    }
}

// ---------------------------------------------------------------- GEMM + copy
// Persistent CTAs. Work units = GEMM tiles + copy units, Bresenham-interleaved
// so ~40% of CTAs at any instant do DRAM copy while ~60% do MMAs (true overlap).
__global__ __launch_bounds__(GEMM_THREADS, 2) void k_gemm(
    const int* __restrict__ token, const int* __restrict__ need,
    const float* __restrict__ emb, const float* __restrict__ bias,
    float* __restrict__ out)
{
    const int cnt = g_cnt;
    const int is64 = g_tok64;
    const int cnt_pad = (cnt + BM - 1) & ~(BM - 1);
    const int n_mt = cnt_pad / BM;
    const int ntiles = n_mt * NTILE_N;
    const int ntotal = ntiles + NCOPY;

    extern __shared__ uint32_t smem[];   // 2 stages x (A 16KB | B 12KB)

    const int tid  = threadIdx.x;
    const int lane = tid & 31;
    const int wid  = tid >> 5;           // 0..5
    const int wm2  = wid / 3;            // 0..1 (M)
    const int wn   = wid - wm2 * 3;      // 0..2 (N)

    #define ISSUE(c, s)                                                          \
    {                                                                            \
        const uint32_t dstA = smem_u32(smem) + (s) * STAGE_BYTES;                \
        const uint32_t dstB = dstA + A_STAGE_BYTES;                              \
        _Pragma("unroll")                                                        \
        for (int j = 0; j < 6; j++) {            /* A: 1024 x 16B */             \
            const int idx = tid + j * GEMM_THREADS;                              \
            if (idx < 1024) {                                                    \
                const int piece = idx >> 7, off = idx & 127;                     \
                const uint4* src =                                               \
                    Ap + (size_t)((mtile * 8 + piece) * NKS + (c) * 4) * 32 + off; \
                cp16(dstA + piece * 2048 + off * 16, src);                       \
            }                                                                    \
        }                                                                        \
        _Pragma("unroll")                                                        \
        for (int j = 0; j < 4; j++) {            /* B: 768 x 16B (exact) */      \
            const int idx = tid + j * GEMM_THREADS;                              \
            const int piece = idx >> 7, off = idx & 127;                         \
            const uint4* src =                                                   \
                Wp + (size_t)((n16_0 + piece) * NKS + (c) * 4) * 32 + off;       \
            cp16(dstB + piece * 2048 + off * 16, src);                           \
        }                                                                        \
        asm volatile("cp.async.commit_group;\n" ::: "memory");                   \
    }

    for (int w = blockIdx.x; w < ntotal; w += GEMM_GRID) {
        // Bresenham split: exact NCOPY copy units spread uniformly among tiles.
        const int cprev = (int)(((long long)w * NCOPY) / ntotal);
        const int cnext = (int)(((long long)(w + 1) * NCOPY) / ntotal);
        if (cnext == cprev) {
            // ---------------- GEMM tile (config unchanged since R11)
            const int t_idx = w - cprev;
            const int mtile = t_idx / NTILE_N;
            const int nt    = t_idx - mtile * NTILE_N;
            const int n16_0 = nt * (BN / 16);
            const int n0    = nt * BN;

            float acc[4][4][4];
            #pragma unroll
            for (int i = 0; i < 4; i++)
                #pragma unroll
                for (int j = 0; j < 4; j++)
                    #pragma unroll
                    for (int r = 0; r < 4; r++) acc[i][j][r] = 0.0f;

            ISSUE(0, 0)

            for (int c = 0; c < NCH; c++) {
                if (c + 1 < NCH) {
                    ISSUE(c + 1, (c + 1) & 1)
                    asm volatile("cp.async.wait_group 1;\n" ::: "memory");
                } else {
                    asm volatile("cp.async.wait_group 0;\n" ::: "memory");
                }
                __syncthreads();

                const uint32_t* aS = smem + (c & 1) * (STAGE_BYTES / 4);
                const uint32_t* bS = aS + (A_STAGE_BYTES / 4);
                #pragma unroll
                for (int ks = 0; ks < 4; ks++) {
                    uint4 a[4], b[2];
                    #pragma unroll
                    for (int fm = 0; fm < 4; fm++)
                        a[fm] = *(const uint4*)(aS + ((wm2 * 4 + fm) * 512 + ks * 128 + lane * 4));
                    #pragma unroll
                    for (int g = 0; g < 2; g++)
                        b[g] = *(const uint4*)(bS + ((wn * 2 + g) * 512 + ks * 128 + lane * 4));
                    #pragma unroll
                    for (int fm = 0; fm < 4; fm++) {
                        mma_f16(acc[fm][0], a[fm], b[0].x, b[0].y);
                        mma_f16(acc[fm][1], a[fm], b[0].z, b[0].w);
                        mma_f16(acc[fm][2], a[fm], b[1].x, b[1].y);
                        mma_f16(acc[fm][3], a[fm], b[1].z, b[1].w);
                    }
                }
                __syncthreads();
            }

            // epilogue: bias + scatter
            #pragma unroll
            for (int fm = 0; fm < 4; fm++) {
                const int r0 = mtile * BM + wm2 * 64 + fm * 16 + (lane >> 2);
                const int r1 = r0 + 8;
                #pragma unroll
                for (int fn = 0; fn < 4; fn++) {
                    const int g = fn >> 1, sub = fn & 1;
                    const int col = n0 + (wn * 2 + g) * 16 + sub * 8 + (lane & 3) * 2;
                    const float b0 = bias[col], b1 = bias[col + 1];
                    if (r0 < cnt) {
                        const int p = g_list[r0];
                        float2 v = make_float2(acc[fm][fn][0] + b0, acc[fm][fn][1] + b1);
                        *(float2*)&out[(size_t)p * DIM + col] = v;
                    }
                    if (r1 < cnt) {
                        const int p = g_list[r1];
                        float2 v = make_float2(acc[fm][fn][2] + b0, acc[fm][fn][3] + b1);
                        *(float2*)&out[(size_t)p * DIM + col] = v;
                    }
                }
            }
        } else {
            // ---------------- copy unit: 48 rows, 8 rows per warp
            const int base = cprev * COPY_ROWS + wid * 8;
            #pragma unroll 1
            for (int r = 0; r < 8; r++) {
                const int p = base + r;
                if (p >= NTOK) break;
                const int t = is64 ? token[2 * p] : token[p];
                if (t < 0 || t >= VOCAB) continue;
                if (need[t]) continue;               // GEMM wrote these rows
                const float4* src = (const float4*)(emb + (size_t)t * DIM);
                float4* dst = (float4*)(out + (size_t)p * DIM);
                float4 v0 = src[lane];
                float4 v1 = src[lane + 32];
                float4 v2 = src[lane + 64];
                float4 v3 = src[lane + 96];
                float4 v4 = src[lane + 128];
                float4 v5 = src[lane + 160];
                dst[lane]       = v0;
                dst[lane + 32]  = v1;
                dst[lane + 64]  = v2;
                dst[lane + 96]  = v3;
                dst[lane + 128] = v4;
                dst[lane + 160] = v5;
            }
        }
    }
    #undef ISSUE
}

// ---------------------------------------------------------------- launch
extern "C" void kernel_launch(void* const* d_in, const int* in_sizes, int n_in,
                              void* d_out, int out_size) {
    const int*   token = (const int*)d_in[0];   // int32 or int64 (auto-detected)
    const int*   need  = (const int*)d_in[1];
    const float* emb   = (const float*)d_in[2];
    const float* W     = (const float*)d_in[3];
    const float* bias  = (const float*)d_in[4];
    float*       out   = (float*)d_out;

    cudaFuncSetAttribute(k_gemm, cudaFuncAttributeMaxDynamicSharedMemorySize, GEMM_SMEM);

    k_init<<<1, 1>>>();
    k_compact<<<NB_CMP + NB_WPACK, 256>>>(token, need, W);
    k_pack<<<NB_PACK, 256>>>(emb);
    k_gemm<<<GEMM_GRID, GEMM_THREADS, GEMM_SMEM>>>(token, need, emb, bias, out);
}

// round 15
// speedup vs baseline: 1.5308x; 1.5308x over previous
#include <cuda_runtime.h>
#include <cuda_fp16.h>
#include <cstdint>

#define VOCAB 50000
#define DIM   768
#define NTOK  16384
#define BM    128
#define BN    96
#define KCH   64                       // K per pipeline chunk (4 k16-steps)
#define NCH   (DIM / KCH)              // 12
#define NKS   (DIM / 16)               // 48 k16-steps per row
#define NM16  (NTOK / 16)              // 1024 fragment row-groups
#define NTILE_N (DIM / BN)             // 8
#define A_STAGE_BYTES (BM * KCH * 2)   // 16 KB (fp16)
#define B_STAGE_BYTES (BN * KCH * 2)   // 12 KB
#define STAGE_BYTES   (A_STAGE_BYTES + B_STAGE_BYTES)   // 28 KB
#define GEMM_SMEM     (2 * STAGE_BYTES)   // 56 KB -> 2 CTAs/SM
#define GEMM_GRID     296              // persistent: 2 CTAs/SM
#define TILE_CTAS     256              // 512 tiles -> exactly 2 per CTA
#define COPY_CTAS     (GEMM_GRID - TILE_CTAS)   // 40 dedicated copy CTAs
#define GEMM_THREADS  192              // 6 warps: 2(M) x 3(N), warp tile 64x32
#define COPY_ROWS 48                   // rows per copy work unit (8/warp, 6 warps)
#define NCOPY ((NTOK + COPY_ROWS - 1) / COPY_ROWS)   // 342

// compact kernel: blocks [0,64) compact, [64,64+288) W-pack
#define NB_CMP   (NTOK / 256)          // 64
#define NB_WPACK ((48 * NKS * 32) / 256)  // 288
#define NB_PACK  (NM16 / 2)            // 512: A-pack, 2 m16-groups per block

__device__ int g_cnt;
__device__ int g_tok64;               // 1 if token buffer is int64
__device__ int g_list[NTOK];          // token position (output row)
__device__ int g_tok[NTOK];           // token id (embedding row)
// Fragment-packed fp16 operands for mma.sync m16n8k16 (row.col)
__device__ uint4 Ap[NM16 * NKS * 32];
__device__ uint4 Wp[(DIM / 16) * NKS * 32];

// ---------------------------------------------------------------- utilities
__device__ __forceinline__ uint32_t f2h2(float x, float y) {
    __half2 h = __floats2half2_rn(x, y);
    return *(uint32_t*)&h;
}
__device__ __forceinline__ uint32_t smem_u32(const void* p) {
    uint32_t a;
    asm("{ .reg .u64 t; cvta.to.shared.u64 t, %1; cvt.u32.u64 %0, t; }" : "=r"(a) : "l"(p));
    return a;
}
__device__ __forceinline__ void cp16(uint32_t dst, const void* src) {
    asm volatile("cp.async.cg.shared.global [%0], [%1], 16;\n" :: "r"(dst), "l"(src));
}
__device__ __forceinline__ void mma_f16(float c[4], uint4 a, uint32_t b0, uint32_t b1) {
    asm volatile(
        "mma.sync.aligned.m16n8k16.row.col.f32.f16.f16.f32 "
        "{%0,%1,%2,%3}, {%4,%5,%6,%7}, {%8,%9}, {%0,%1,%2,%3};\n"
        : "+f"(c[0]), "+f"(c[1]), "+f"(c[2]), "+f"(c[3])
        : "r"(a.x), "r"(a.y), "r"(a.z), "r"(a.w), "r"(b0), "r"(b1));
}

// ---------------------------------------------------------------- init
__global__ void k_init() { g_cnt = 0; }

// ---------------------------------------------------------------- compact + W-pack
// Blocks [0,NB_CMP): per-block dtype detect (L2-hot) + 1 token/thread compact.
// Blocks [NB_CMP,NB_CMP+NB_WPACK): W fragment pack (independent of compact).
__global__ void k_compact(const int* __restrict__ token, const int* __restrict__ need,
                          const float* __restrict__ W) {
    const int tid = threadIdx.x;
    if (blockIdx.x < NB_CMP) {
        int odd = (tid < 128) ? token[tid * 2 + 1] : 0;
        int any = __syncthreads_or(odd != 0);
        const int is64 = !any;
        if (blockIdx.x == 0 && tid == 0) g_tok64 = is64;

        const int p = blockIdx.x * 256 + tid;        // covers NTOK exactly
        const int t = is64 ? token[2 * p] : token[p];
        if (t >= 0 && t < VOCAB && need[t]) {
            const int pos = atomicAdd(&g_cnt, 1);
            g_list[pos] = p;
            g_tok[pos]  = t;
        }
    } else {
        const int gi = (blockIdx.x - NB_CMP) * 256 + tid;  // 48*48*32
        const int lw  = gi & 31;
        const int ks  = (gi >> 5) % NKS;
        const int n16 = gi / (NKS * 32);
        const int na = n16 * 16 + (lw >> 2);
        const int nb = na + 8;
        const int k0 = ks * 16 + (lw & 3) * 2;
        uint4 o;
        o.x = f2h2(W[(size_t)k0 * DIM + na],       W[(size_t)(k0 + 1) * DIM + na]);
        o.y = f2h2(W[(size_t)(k0 + 8) * DIM + na], W[(size_t)(k0 + 9) * DIM + na]);
        o.z = f2h2(W[(size_t)k0 * DIM + nb],       W[(size_t)(k0 + 1) * DIM + nb]);
        o.w = f2h2(W[(size_t)(k0 + 8) * DIM + nb], W[(size_t)(k0 + 9) * DIM + nb]);
        Wp[(size_t)(n16 * NKS + ks) * 32 + lw] = o;
    }
}

// ---------------------------------------------------------------- A pack
// 512 blocks x 256: 2 m16-groups per block, 4 warps each, 8 gathers in flight.
__global__ void k_pack(const float* __restrict__ emb) {
    const int bid  = blockIdx.x;
    const int tid  = threadIdx.x;
    const int wid  = tid >> 5;
    const int lane = tid & 31;

    const int cnt = g_cnt;
    const int cnt_pad = (cnt + BM - 1) & ~(BM - 1);
    const int m16 = bid * 2 + (wid >> 2);
    if (m16 * 16 >= cnt_pad) return;
    const int wg = wid & 3;                      // warp within group
    const int lr = lane >> 2, lk = lane & 3;
    const int r0 = m16 * 16 + lr, r1 = r0 + 8;
    const bool v0 = r0 < cnt, v1 = r1 < cnt;
    const float* e0 = emb + (size_t)(v0 ? g_tok[r0] : 0) * DIM;
    const float* e1 = emb + (size_t)(v1 ? g_tok[r1] : 0) * DIM;
    const float2 z2 = make_float2(0.f, 0.f);
    #pragma unroll
    for (int j = 0; j < NKS / 4; j += 2) {       // 12 ksteps, 2 at a time
        const int ksA = wg * (NKS / 4) + j;
        const int kA = ksA * 16 + lk * 2;
        const int kB = kA + 16;
        const float2 a0 = v0 ? *(const float2*)(e0 + kA)     : z2;
        const float2 a2 = v0 ? *(const float2*)(e0 + kA + 8) : z2;
        const float2 a1 = v1 ? *(const float2*)(e1 + kA)     : z2;
        const float2 a3 = v1 ? *(const float2*)(e1 + kA + 8) : z2;
        const float2 b0 = v0 ? *(const float2*)(e0 + kB)     : z2;
        const float2 b2 = v0 ? *(const float2*)(e0 + kB + 8) : z2;
        const float2 b1 = v1 ? *(const float2*)(e1 + kB)     : z2;
        const float2 b3 = v1 ? *(const float2*)(e1 + kB + 8) : z2;
        uint4 oA, oB;
        oA.x = f2h2(a0.x, a0.y); oA.y = f2h2(a1.x, a1.y);
        oA.z = f2h2(a2.x, a2.y); oA.w = f2h2(a3.x, a3.y);
        oB.x = f2h2(b0.x, b0.y); oB.y = f2h2(b1.x, b1.y);
        oB.z = f2h2(b2.x, b2.y); oB.w = f2h2(b3.x, b3.y);
        Ap[(size_t)(m16 * NKS + ksA) * 32 + lane]     = oA;
        Ap[(size_t)(m16 * NKS + ksA + 1) * 32 + lane] = oB;
    }
}

// ---------------------------------------------------------------- GEMM + copy
// Persistent CTAs, statically partitioned: TILE_CTAS run GEMM tiles (mtile-major,
// ntile fastest), COPY_CTAS run only copy units concurrently (DRAM overlap).
__global__ __launch_bounds__(GEMM_THREADS, 2) void k_gemm(
    const int* __restrict__ token, const int* __restrict__ need,
    const float* __restrict__ emb, const float* __restrict__ bias,
    float* __restrict__ out)
{
    const int cnt = g_cnt;
    const int is64 = g_tok64;
    const int cnt_pad = (cnt + BM - 1) & ~(BM - 1);
    const int n_mt = cnt_pad / BM;
    const int ntiles = n_mt * NTILE_N;

    extern __shared__ uint32_t smem[];   // 2 stages x (A 16KB | B 12KB)

    const int tid  = threadIdx.x;
    const int lane = tid & 31;
    const int wid  = tid >> 5;           // 0..5
    const int wm2  = wid / 3;            // 0..1 (M)
    const int wn   = wid - wm2 * 3;      // 0..2 (N)

    #define ISSUE(c, s)                                                          \
    {                                                                            \
        const uint32_t dstA = smem_u32(smem) + (s) * STAGE_BYTES;                \
        const uint32_t dstB = dstA + A_STAGE_BYTES;                              \
        _Pragma("unroll")                                                        \
        for (int j = 0; j < 6; j++) {            /* A: 1024 x 16B */             \
            const int idx = tid + j * GEMM_THREADS;                              \
            if (idx < 1024) {                                                    \
                const int piece = idx >> 7, off = idx & 127;                     \
                const uint4* src =                                               \
                    Ap + (size_t)((mtile * 8 + piece) * NKS + (c) * 4) * 32 + off; \
                cp16(dstA + piece * 2048 + off * 16, src);                       \
            }                                                                    \
        }                                                                        \
        _Pragma("unroll")                                                        \
        for (int j = 0; j < 4; j++) {            /* B: 768 x 16B (exact) */      \
            const int idx = tid + j * GEMM_THREADS;                              \
            const int piece = idx >> 7, off = idx & 127;                         \
            const uint4* src =                                                   \
                Wp + (size_t)((n16_0 + piece) * NKS + (c) * 4) * 32 + off;       \
            cp16(dstB + piece * 2048 + off * 16, src);                           \
        }                                                                        \
        asm volatile("cp.async.commit_group;\n" ::: "memory");                   \
    }

    if (blockIdx.x < TILE_CTAS) {
        for (int w = blockIdx.x; w < ntiles; w += TILE_CTAS) {
            // ---------------- GEMM tile (config unchanged since R11)
            const int mtile = w / NTILE_N;
            const int nt    = w - mtile * NTILE_N;
            const int n16_0 = nt * (BN / 16);
            const int n0    = nt * BN;

            float acc[4][4][4];
            #pragma unroll
            for (int i = 0; i < 4; i++)
                #pragma unroll
                for (int j = 0; j < 4; j++)
                    #pragma unroll
                    for (int r = 0; r < 4; r++) acc[i][j][r] = 0.0f;

            ISSUE(0, 0)

            for (int c = 0; c < NCH; c++) {
                if (c + 1 < NCH) {
                    ISSUE(c + 1, (c + 1) & 1)
                    asm volatile("cp.async.wait_group 1;\n" ::: "memory");
                } else {
                    asm volatile("cp.async.wait_group 0;\n" ::: "memory");
                }
                __syncthreads();

                const uint32_t* aS = smem + (c & 1) * (STAGE_BYTES / 4);
                const uint32_t* bS = aS + (A_STAGE_BYTES / 4);
                #pragma unroll
                for (int ks = 0; ks < 4; ks++) {
                    uint4 a[4], b[2];
                    #pragma unroll
                    for (int fm = 0; fm < 4; fm++)
                        a[fm] = *(const uint4*)(aS + ((wm2 * 4 + fm) * 512 + ks * 128 + lane * 4));
                    #pragma unroll
                    for (int g = 0; g < 2; g++)
                        b[g] = *(const uint4*)(bS + ((wn * 2 + g) * 512 + ks * 128 + lane * 4));
                    #pragma unroll
                    for (int fm = 0; fm < 4; fm++) {
                        mma_f16(acc[fm][0], a[fm], b[0].x, b[0].y);
                        mma_f16(acc[fm][1], a[fm], b[0].z, b[0].w);
                        mma_f16(acc[fm][2], a[fm], b[1].x, b[1].y);
                        mma_f16(acc[fm][3], a[fm], b[1].z, b[1].w);
                    }
                }
                __syncthreads();
            }

            // epilogue: bias + scatter
            #pragma unroll
            for (int fm = 0; fm < 4; fm++) {
                const int r0 = mtile * BM + wm2 * 64 + fm * 16 + (lane >> 2);
                const int r1 = r0 + 8;
                #pragma unroll
                for (int fn = 0; fn < 4; fn++) {
                    const int g = fn >> 1, sub = fn & 1;
                    const int col = n0 + (wn * 2 + g) * 16 + sub * 8 + (lane & 3) * 2;
                    const float b0 = bias[col], b1 = bias[col + 1];
                    if (r0 < cnt) {
                        const int p = g_list[r0];
                        float2 v = make_float2(acc[fm][fn][0] + b0, acc[fm][fn][1] + b1);
                        *(float2*)&out[(size_t)p * DIM + col] = v;
                    }
                    if (r1 < cnt) {
                        const int p = g_list[r1];
                        float2 v = make_float2(acc[fm][fn][2] + b0, acc[fm][fn][3] + b1);
                        *(float2*)&out[(size_t)p * DIM + col] = v;
                    }
                }
            }
        }
    } else {
        // ---------------- dedicated copy CTAs: run concurrently with tiles
        const int cbid = blockIdx.x - TILE_CTAS;     // 0..COPY_CTAS-1
        for (int u = cbid; u < NCOPY; u += COPY_CTAS) {
            const int base = u * COPY_ROWS + wid * 8;
            #pragma unroll 1
            for (int r = 0; r < 8; r++) {
                const int p = base + r;
                if (p >= NTOK) break;
                const int t = is64 ? token[2 * p] : token[p];
                if (t < 0 || t >= VOCAB) continue;
                if (need[t]) continue;               // GEMM wrote these rows
                const float4* src = (const float4*)(emb + (size_t)t * DIM);
                float4* dst = (float4*)(out + (size_t)p * DIM);
                float4 v0 = src[lane];
                float4 v1 = src[lane + 32];
                float4 v2 = src[lane + 64];
                float4 v3 = src[lane + 96];
                float4 v4 = src[lane + 128];
                float4 v5 = src[lane + 160];
                dst[lane]       = v0;
                dst[lane + 32]  = v1;
                dst[lane + 64]  = v2;
                dst[lane + 96]  = v3;
                dst[lane + 128] = v4;
                dst[lane + 160] = v5;
            }
        }
    }
    #undef ISSUE
}

// ---------------------------------------------------------------- launch
extern "C" void kernel_launch(void* const* d_in, const int* in_sizes, int n_in,
                              void* d_out, int out_size) {
    const int*   token = (const int*)d_in[0];   // int32 or int64 (auto-detected)
    const int*   need  = (const int*)d_in[1];
    const float* emb   = (const float*)d_in[2];
    const float* W     = (const float*)d_in[3];
    const float* bias  = (const float*)d_in[4];
    float*       out   = (float*)d_out;

    cudaFuncSetAttribute(k_gemm, cudaFuncAttributeMaxDynamicSharedMemorySize, GEMM_SMEM);

    k_init<<<1, 1>>>();
    k_compact<<<NB_CMP + NB_WPACK, 256>>>(token, need, W);
    k_pack<<<NB_PACK, 256>>>(emb);
    k_gemm<<<GEMM_GRID, GEMM_THREADS, GEMM_SMEM>>>(token, need, emb, bias, out);
}

// round 17
// speedup vs baseline: 1.5760x; 1.0295x over previous
#include <cuda_runtime.h>
#include <cuda_fp16.h>
#include <cstdint>

#define VOCAB 50000
#define DIM   768
#define NTOK  16384
#define BM    128
#define BN    96
#define KCH   64                       // K per pipeline chunk (4 k16-steps)
#define NCH   (DIM / KCH)              // 12
#define NKS   (DIM / 16)               // 48 k16-steps per row
#define NM16  (NTOK / 16)              // 1024 fragment row-groups
#define NTILE_N (DIM / BN)             // 8
#define A_STAGE_BYTES (BM * KCH * 2)   // 16 KB (fp16)
#define B_STAGE_BYTES (BN * KCH * 2)   // 12 KB
#define STAGE_BYTES   (A_STAGE_BYTES + B_STAGE_BYTES)   // 28 KB
#define GEMM_SMEM     (3 * STAGE_BYTES)   // 84 KB -> still 2 CTAs/SM
#define GEMM_GRID     296              // persistent: 2 CTAs/SM, all resident
#define GEMM_THREADS  192              // 6 warps: 2(M) x 3(N), warp tile 64x32

// k_compact grid ranges: compact | W-pack | copy (copy independent of compact)
#define NB_CMP   (NTOK / 256)          // 64
#define NB_WPACK ((48 * NKS * 32) / 256)  // 288
#define NB_COPY  (NTOK / 64)           // 256: 64 rows per block (8 rows/warp)
#define NB_CTOT  (NB_CMP + NB_WPACK + NB_COPY)

#define NB_PACK  (NM16 / 2)            // 512: A-pack, 2 m16-groups per block

__device__ int g_cnt;                 // reset to 0 by previous launch's k_gemm
__device__ int g_tok64;               // 1 if token buffer is int64
__device__ int g_list[NTOK];          // token position (output row)
__device__ int g_tok[NTOK];           // token id (embedding row)
// Fragment-packed fp16 operands for mma.sync m16n8k16 (row.col)
__device__ uint4 Ap[NM16 * NKS * 32];
__device__ uint4 Wp[(DIM / 16) * NKS * 32];

// ---------------------------------------------------------------- utilities
__device__ __forceinline__ uint32_t f2h2(float x, float y) {
    __half2 h = __floats2half2_rn(x, y);
    return *(uint32_t*)&h;
}
__device__ __forceinline__ uint32_t smem_u32(const void* p) {
    uint32_t a;
    asm("{ .reg .u64 t; cvta.to.shared.u64 t, %1; cvt.u32.u64 %0, t; }" : "=r"(a) : "l"(p));
    return a;
}
__device__ __forceinline__ void cp16(uint32_t dst, const void* src) {
    asm volatile("cp.async.cg.shared.global [%0], [%1], 16;\n" :: "r"(dst), "l"(src));
}
__device__ __forceinline__ void mma_f16(float c[4], uint4 a, uint32_t b0, uint32_t b1) {
    asm volatile(
        "mma.sync.aligned.m16n8k16.row.col.f32.f16.f16.f32 "
        "{%0,%1,%2,%3}, {%4,%5,%6,%7}, {%8,%9}, {%0,%1,%2,%3};\n"
        : "+f"(c[0]), "+f"(c[1]), "+f"(c[2]), "+f"(c[3])
        : "r"(a.x), "r"(a.y), "r"(a.z), "r"(a.w), "r"(b0), "r"(b1));
}

// ---------------------------------------------------------------- compact + W-pack + copy
// Blocks [0,NB_CMP): per-block dtype detect (L2-hot) + 1 token/thread compact.
// Blocks [NB_CMP,+NB_WPACK): W fragment pack (independent of compact).
// Blocks [NB_CMP+NB_WPACK,+NB_COPY): copy non-mapped rows (independent of compact):
//   overlaps the DRAM-heavy copy with the tiny compact/wpack work.
__global__ void k_compact(const int* __restrict__ token, const int* __restrict__ need,
                          const float* __restrict__ W, const float* __restrict__ emb,
                          float4* __restrict__ out) {
    const int tid = threadIdx.x;
    if (blockIdx.x < NB_CMP) {
        int odd = (tid < 128) ? token[tid * 2 + 1] : 0;
        int any = __syncthreads_or(odd != 0);
        const int is64 = !any;
        if (blockIdx.x == 0 && tid == 0) g_tok64 = is64;

        const int p = blockIdx.x * 256 + tid;        // covers NTOK exactly
        const int t = is64 ? token[2 * p] : token[p];
        if (t >= 0 && t < VOCAB && need[t]) {
            const int pos = atomicAdd(&g_cnt, 1);
            g_list[pos] = p;
            g_tok[pos]  = t;
        }
    } else if (blockIdx.x < NB_CMP + NB_WPACK) {
        const int gi = (blockIdx.x - NB_CMP) * 256 + tid;  // 48*48*32
        const int lw  = gi & 31;
        const int ks  = (gi >> 5) % NKS;
        const int n16 = gi / (NKS * 32);
        const int na = n16 * 16 + (lw >> 2);
        const int nb = na + 8;
        const int k0 = ks * 16 + (lw & 3) * 2;
        uint4 o;
        o.x = f2h2(W[(size_t)k0 * DIM + na],       W[(size_t)(k0 + 1) * DIM + na]);
        o.y = f2h2(W[(size_t)(k0 + 8) * DIM + na], W[(size_t)(k0 + 9) * DIM + na]);
        o.z = f2h2(W[(size_t)k0 * DIM + nb],       W[(size_t)(k0 + 1) * DIM + nb]);
        o.w = f2h2(W[(size_t)(k0 + 8) * DIM + nb], W[(size_t)(k0 + 9) * DIM + nb]);
        Wp[(size_t)(n16 * NKS + ks) * 32 + lw] = o;
    } else {
        // copy branch: own dtype detect, then 64 rows per block, 8 per warp
        int odd = (tid < 128) ? token[tid * 2 + 1] : 0;
        int any = __syncthreads_or(odd != 0);
        const int is64 = !any;
        const int wid = tid >> 5, lane = tid & 31;   // 8 warps
        const int base = (blockIdx.x - NB_CMP - NB_WPACK) * 64 + wid * 8;
        #pragma unroll 1
        for (int r = 0; r < 8; r++) {
            const int p = base + r;
            const int t = is64 ? token[2 * p] : token[p];
            if (t < 0 || t >= VOCAB) continue;
            if (need[t]) continue;                   // GEMM writes these rows
            const float4* src = (const float4*)(emb + (size_t)t * DIM);
            float4* dst = (float4*)((float*)out + (size_t)p * DIM);
            float4 v0 = src[lane];
            float4 v1 = src[lane + 32];
            float4 v2 = src[lane + 64];
            float4 v3 = src[lane + 96];
            float4 v4 = src[lane + 128];
            float4 v5 = src[lane + 160];
            dst[lane]       = v0;
            dst[lane + 32]  = v1;
            dst[lane + 64]  = v2;
            dst[lane + 96]  = v3;
            dst[lane + 128] = v4;
            dst[lane + 160] = v5;
        }
    }
}

// ---------------------------------------------------------------- A pack
// 512 blocks x 256: 2 m16-groups per block, 4 warps each, 8 gathers in flight.
__global__ void k_pack(const float* __restrict__ emb) {
    const int bid  = blockIdx.x;
    const int tid  = threadIdx.x;
    const int wid  = tid >> 5;
    const int lane = tid & 31;

    const int cnt = g_cnt;
    const int cnt_pad = (cnt + BM - 1) & ~(BM - 1);
    const int m16 = bid * 2 + (wid >> 2);
    if (m16 * 16 >= cnt_pad) return;
    const int wg = wid & 3;                      // warp within group
    const int lr = lane >> 2, lk = lane & 3;
    const int r0 = m16 * 16 + lr, r1 = r0 + 8;
    const bool v0 = r0 < cnt, v1 = r1 < cnt;
    const float* e0 = emb + (size_t)(v0 ? g_tok[r0] : 0) * DIM;
    const float* e1 = emb + (size_t)(v1 ? g_tok[r1] : 0) * DIM;
    const float2 z2 = make_float2(0.f, 0.f);
    #pragma unroll
    for (int j = 0; j < NKS / 4; j += 2) {       // 12 ksteps, 2 at a time
        const int ksA = wg * (NKS / 4) + j;
        const int kA = ksA * 16 + lk * 2;
        const int kB = kA + 16;
        const float2 a0 = v0 ? *(const float2*)(e0 + kA)     : z2;
        const float2 a2 = v0 ? *(const float2*)(e0 + kA + 8) : z2;
        const float2 a1 = v1 ? *(const float2*)(e1 + kA)     : z2;
        const float2 a3 = v1 ? *(const float2*)(e1 + kA + 8) : z2;
        const float2 b0 = v0 ? *(const float2*)(e0 + kB)     : z2;
        const float2 b2 = v0 ? *(const float2*)(e0 + kB + 8) : z2;
        const float2 b1 = v1 ? *(const float2*)(e1 + kB)     : z2;
        const float2 b3 = v1 ? *(const float2*)(e1 + kB + 8) : z2;
        uint4 oA, oB;
        oA.x = f2h2(a0.x, a0.y); oA.y = f2h2(a1.x, a1.y);
        oA.z = f2h2(a2.x, a2.y); oA.w = f2h2(a3.x, a3.y);
        oB.x = f2h2(b0.x, b0.y); oB.y = f2h2(b1.x, b1.y);
        oB.z = f2h2(b2.x, b2.y); oB.w = f2h2(b3.x, b3.y);
        Ap[(size_t)(m16 * NKS + ksA) * 32 + lane]     = oA;
        Ap[(size_t)(m16 * NKS + ksA + 1) * 32 + lane] = oB;
    }
}

// ---------------------------------------------------------------- GEMM (pure tiles)
// Persistent CTAs; 3-stage cp.async pipeline, ONE barrier per chunk (the stage
// written by ISSUE(c+2) is never concurrently read; next iteration's barrier
// orders reads of stage c%3 before ISSUE(c+3) rewrites it).
// Block 0 resets g_cnt at its end for the NEXT launch (all CTAs are resident
// and latch g_cnt at entry long before block 0 finishes its ~35us of tiles).
__global__ __launch_bounds__(GEMM_THREADS, 2) void k_gemm(
    const float* __restrict__ bias, float* __restrict__ out)
{
    const int cnt = g_cnt;
    const int cnt_pad = (cnt + BM - 1) & ~(BM - 1);
    const int n_mt = cnt_pad / BM;
    const int ntiles = n_mt * NTILE_N;

    extern __shared__ uint32_t smem[];   // 3 stages x (A 16KB | B 12KB)

    const int tid  = threadIdx.x;
    const int lane = tid & 31;
    const int wid  = tid >> 5;           // 0..5
    const int wm2  = wid / 3;            // 0..1 (M)
    const int wn   = wid - wm2 * 3;      // 0..2 (N)

    #define ISSUE(c, s)                                                          \
    {                                                                            \
        const uint32_t dstA = smem_u32(smem) + (s) * STAGE_BYTES;                \
        const uint32_t dstB = dstA + A_STAGE_BYTES;                              \
        _Pragma("unroll")                                                        \
        for (int j = 0; j < 6; j++) {            /* A: 1024 x 16B */             \
            const int idx = tid + j * GEMM_THREADS;                              \
            if (idx < 1024) {                                                    \
                const int piece = idx >> 7, off = idx & 127;                     \
                const uint4* src =                                               \
                    Ap + (size_t)((mtile * 8 + piece) * NKS + (c) * 4) * 32 + off; \
                cp16(dstA + piece * 2048 + off * 16, src);                       \
            }                                                                    \
        }                                                                        \
        _Pragma("unroll")                                                        \
        for (int j = 0; j < 4; j++) {            /* B: 768 x 16B (exact) */      \
            const int idx = tid + j * GEMM_THREADS;                              \
            const int piece = idx >> 7, off = idx & 127;                         \
            const uint4* src =                                                   \
                Wp + (size_t)((n16_0 + piece) * NKS + (c) * 4) * 32 + off;       \
            cp16(dstB + piece * 2048 + off * 16, src);                           \
        }                                                                        \
        asm volatile("cp.async.commit_group;\n" ::: "memory");                   \
    }

    for (int w = blockIdx.x; w < ntiles; w += GEMM_GRID) {
        const int mtile = w / NTILE_N;
        const int nt    = w - mtile * NTILE_N;
        const int n16_0 = nt * (BN / 16);
        const int n0    = nt * BN;

        float acc[4][4][4];
        #pragma unroll
        for (int i = 0; i < 4; i++)
            #pragma unroll
            for (int j = 0; j < 4; j++)
                #pragma unroll
                for (int r = 0; r < 4; r++) acc[i][j][r] = 0.0f;

        ISSUE(0, 0)
        ISSUE(1, 1)

        for (int c = 0; c < NCH; c++) {
            if (c + 1 < NCH) asm volatile("cp.async.wait_group 1;\n" ::: "memory");
            else             asm volatile("cp.async.wait_group 0;\n" ::: "memory");
            __syncthreads();   // chunk c visible; also orders prior-chunk reads
                               // before the rewrite below
            if (c + 2 < NCH) ISSUE(c + 2, (c + 2) % 3)

            const uint32_t* aS = smem + (c % 3) * (STAGE_BYTES / 4);
            const uint32_t* bS = aS + (A_STAGE_BYTES / 4);
            #pragma unroll
            for (int ks = 0; ks < 4; ks++) {
                uint4 a[4], b[2];
                #pragma unroll
                for (int fm = 0; fm < 4; fm++)
                    a[fm] = *(const uint4*)(aS + ((wm2 * 4 + fm) * 512 + ks * 128 + lane * 4));
                #pragma unroll
                for (int g = 0; g < 2; g++)
                    b[g] = *(const uint4*)(bS + ((wn * 2 + g) * 512 + ks * 128 + lane * 4));
                #pragma unroll
                for (int fm = 0; fm < 4; fm++) {
                    mma_f16(acc[fm][0], a[fm], b[0].x, b[0].y);
                    mma_f16(acc[fm][1], a[fm], b[0].z, b[0].w);
                    mma_f16(acc[fm][2], a[fm], b[1].x, b[1].y);
                    mma_f16(acc[fm][3], a[fm], b[1].z, b[1].w);
                }
            }
        }
        __syncthreads();   // tile done before stage 0/1 reuse by next tile's ISSUE

        // epilogue: bias + scatter
        #pragma unroll
        for (int fm = 0; fm < 4; fm++) {
            const int r0 = mtile * BM + wm2 * 64 + fm * 16 + (lane >> 2);
            const int r1 = r0 + 8;
            #pragma unroll
            for (int fn = 0; fn < 4; fn++) {
                const int g = fn >> 1, sub = fn & 1;
                const int col = n0 + (wn * 2 + g) * 16 + sub * 8 + (lane & 3) * 2;
                const float b0 = bias[col], b1 = bias[col + 1];
                if (r0 < cnt) {
                    const int p = g_list[r0];
                    float2 v = make_float2(acc[fm][fn][0] + b0, acc[fm][fn][1] + b1);
                    *(float2*)&out[(size_t)p * DIM + col] = v;
                }
                if (r1 < cnt) {
                    const int p = g_list[r1];
                    float2 v = make_float2(acc[fm][fn][2] + b0, acc[fm][fn][3] + b1);
                    *(float2*)&out[(size_t)p * DIM + col] = v;
                }
            }
        }
    }
    #undef ISSUE

    // reset compaction counter for the next launch (stream-ordered visibility)
    if (blockIdx.x == 0 && tid == 0) g_cnt = 0;
}

// ---------------------------------------------------------------- launch
extern "C" void kernel_launch(void* const* d_in, const int* in_sizes, int n_in,
                              void* d_out, int out_size) {
    const int*   token = (const int*)d_in[0];   // int32 or int64 (auto-detected)
    const int*   need  = (const int*)d_in[1];
    const float* emb   = (const float*)d_in[2];
    const float* W     = (const float*)d_in[3];
    const float* bias  = (const float*)d_in[4];
    float*       out   = (float*)d_out;

    cudaFuncSetAttribute(k_gemm, cudaFuncAttributeMaxDynamicSharedMemorySize, GEMM_SMEM);

    k_compact<<<NB_CTOT, 256>>>(token, need, W, emb, (float4*)out);
    k_pack<<<NB_PACK, 256>>>(emb);
    k_gemm<<<GEMM_GRID, GEMM_THREADS, GEMM_SMEM>>>(bias, out);
}